// round 1
// baseline (speedup 1.0000x reference)
#include <cuda_runtime.h>
#include <cstdint>

#define BDIM 256
#define TDIM 1024
#define U    32
#define UNF  6
#define EPSV 1e-8f
#define LOG2E 1.4426950408889634f
#define AMAX 18
#define SMAX 32

// 64 MB scratch for precomputed sensory numerator/denominator per (b,t,unit)
__device__ float2 g_sens[(size_t)BDIM * TDIM * U];

// per-column sparse recurrent synapse lists, layout [k*U + col] for coalescing
__device__ int   g_asrc[AMAX * U];
__device__ float g_aa2[AMAX * U], g_ab2[AMAX * U], g_awe[AMAX * U], g_awd[AMAX * U];
__device__ int   g_na;

// per-column sparse sensory synapse lists
__device__ int   g_ssrc[SMAX * U];
__device__ float g_sa2[SMAX * U], g_sb2[SMAX * U], g_swe[SMAX * U], g_swd[SMAX * U];
__device__ int   g_ns;

__device__ __forceinline__ float ex2f(float x) {
    float r; asm("ex2.approx.ftz.f32 %0, %1;" : "=f"(r) : "f"(x)); return r;
}
__device__ __forceinline__ float rcpf(float x) {
    float r; asm("rcp.approx.ftz.f32 %0, %1;" : "=f"(r) : "f"(x)); return r;
}

// ---------------------------------------------------------------------------
// Setup: build padded per-column sparse lists from the masks (32 threads).
// ---------------------------------------------------------------------------
__global__ void setup_kernel(
    const int* __restrict__ spm, const float* __restrict__ wsyn,
    const float* __restrict__ mu, const float* __restrict__ sg,
    const float* __restrict__ er,
    const int* __restrict__ ssm, const float* __restrict__ sw,
    const float* __restrict__ smu, const float* __restrict__ ssg,
    const float* __restrict__ ser)
{
    int j = threadIdx.x;  // destination column / unit

    // recurrent adjacency
    int cnt = 0;
    for (int i = 0; i < U; i++) {
        int idx = i * U + j;
        if (spm[idx] != 0 && cnt < AMAX) {
            float s = sg[idx];
            g_asrc[cnt * U + j] = i;
            g_aa2[cnt * U + j]  = s * LOG2E;
            g_ab2[cnt * U + j]  = s * mu[idx] * LOG2E;
            g_awe[cnt * U + j]  = wsyn[idx] * er[idx];
            g_awd[cnt * U + j]  = wsyn[idx];
            cnt++;
        }
    }
    for (int k = cnt; k < AMAX; k++) {
        g_asrc[k * U + j] = 0;
        g_aa2[k * U + j] = 0.f; g_ab2[k * U + j] = 0.f;
        g_awe[k * U + j] = 0.f; g_awd[k * U + j] = 0.f;
    }
    int m = cnt;
    #pragma unroll
    for (int o = 16; o > 0; o >>= 1) m = max(m, __shfl_xor_sync(0xffffffffu, m, o));
    if (j == 0) g_na = m;

    // sensory adjacency
    cnt = 0;
    for (int i = 0; i < U; i++) {
        int idx = i * U + j;
        if (ssm[idx] != 0 && cnt < SMAX) {
            float s = ssg[idx];
            g_ssrc[cnt * U + j] = i;
            g_sa2[cnt * U + j]  = s * LOG2E;
            g_sb2[cnt * U + j]  = s * smu[idx] * LOG2E;
            g_swe[cnt * U + j]  = sw[idx] * ser[idx];
            g_swd[cnt * U + j]  = sw[idx];
            cnt++;
        }
    }
    for (int k = cnt; k < SMAX; k++) {
        g_ssrc[k * U + j] = 0;
        g_sa2[k * U + j] = 0.f; g_sb2[k * U + j] = 0.f;
        g_swe[k * U + j] = 0.f; g_swd[k * U + j] = 0.f;
    }
    m = cnt;
    #pragma unroll
    for (int o = 16; o > 0; o >>= 1) m = max(m, __shfl_xor_sync(0xffffffffu, m, o));
    if (j == 0) g_ns = m;
}

// ---------------------------------------------------------------------------
// Precompute: fused dense stack + sensory synapse sums per (b,t).
// One warp per row, 4 rows per 128-thread block. Fully parallel over B*T.
// ---------------------------------------------------------------------------
__global__ void __launch_bounds__(128) sens_kernel(
    const float* __restrict__ x,
    const float* __restrict__ d1w, const float* __restrict__ d1b,
    const float* __restrict__ d2w, const float* __restrict__ d2b,
    const float* __restrict__ iw,  const float* __restrict__ ib)
{
    __shared__ float sh_h1[4][128];
    __shared__ float sh_in[4][32];
    int warp = threadIdx.x >> 5, lane = threadIdx.x & 31;
    size_t row = (size_t)blockIdx.x * 4 + warp;   // < B*T

    float x0 = x[row * 2 + 0];
    float x1 = x[row * 2 + 1];

    // h1 = relu(x @ d1_w + d1_b): each lane computes 4 of the 128 outputs
    #pragma unroll
    for (int r = 0; r < 4; r++) {
        int k = r * 32 + lane;
        float h = fmaf(x0, d1w[k], fmaf(x1, d1w[128 + k], d1b[k]));
        sh_h1[warp][k] = fmaxf(h, 0.f);
    }
    __syncwarp();

    // h2[lane] = h1 @ d2_w[:, lane] + d2_b[lane]
    float acc = d2b[lane];
    #pragma unroll 8
    for (int k = 0; k < 128; k++)
        acc = fmaf(sh_h1[warp][k], d2w[k * 32 + lane], acc);

    float inp = fmaf(acc, iw[lane], ib[lane]);
    sh_in[warp][lane] = inp;
    __syncwarp();

    // sensory synapse sums for column 'lane'
    float num = 0.f, den = 0.f;
    int ns = g_ns;
    for (int k = 0; k < ns; k++) {
        int   src = g_ssrc[k * U + lane];
        float vi  = sh_in[warp][src];
        float arg = g_sb2[k * U + lane] - g_sa2[k * U + lane] * vi;
        float r   = rcpf(1.f + ex2f(arg));   // sigmoid
        num = fmaf(g_swe[k * U + lane], r, num);
        den = fmaf(g_swd[k * U + lane], r, den);
    }
    g_sens[row * U + lane] = make_float2(num, den);
}

// ---------------------------------------------------------------------------
// Sequential scan: one warp per batch, lane = unit. Recurrent synapse params
// in registers (compile-time NA), cross-lane v via shfl.
// ---------------------------------------------------------------------------
template <int NA>
__device__ __forceinline__ void scan_body(
    int lane, int batch,
    const float* __restrict__ gleak, const float* __restrict__ vleak,
    const float* __restrict__ cm,
    const float* __restrict__ ow, const float* __restrict__ ob,
    float* __restrict__ out)
{
    float gl   = gleak[lane];
    float cmt  = cm[lane] * (float)UNF;
    float gv   = gl * vleak[lane];
    float denc = cmt + gl + EPSV;

    int   src[NA]; float a2[NA], b2[NA], we[NA], wd[NA];
    #pragma unroll
    for (int k = 0; k < NA; k++) {
        src[k] = g_asrc[k * U + lane];
        a2[k]  = g_aa2[k * U + lane];
        b2[k]  = g_ab2[k * U + lane];
        we[k]  = g_awe[k * U + lane];
        wd[k]  = g_awd[k * U + lane];
    }

    const float2* sp = g_sens + (size_t)batch * TDIM * U + lane;
    float v = 0.f;
    float2 sv = sp[0];

    for (int t = 0; t < TDIM; t++) {
        int tn = (t + 1 < TDIM) ? (t + 1) : t;
        float2 nxt = sp[(size_t)tn * U];    // prefetch next step, hidden by unfolds

        #pragma unroll
        for (int u = 0; u < UNF; u++) {
            float num = sv.x, den = sv.y;
            #pragma unroll
            for (int k = 0; k < NA; k++) {
                float vs  = __shfl_sync(0xffffffffu, v, src[k]);
                float arg = b2[k] - a2[k] * vs;
                float r   = rcpf(1.f + ex2f(arg));
                num = fmaf(we[k], r, num);
                den = fmaf(wd[k], r, den);
            }
            v = (fmaf(cmt, v, gv) + num) * rcpf(denc + den);
        }
        sv = nxt;
    }

    if (lane == 0) out[batch] = fmaf(v, ow[0], ob[0]);
}

__global__ void __launch_bounds__(64) scan_kernel(
    const float* __restrict__ gleak, const float* __restrict__ vleak,
    const float* __restrict__ cm,
    const float* __restrict__ ow, const float* __restrict__ ob,
    float* __restrict__ out)
{
    int lane  = threadIdx.x & 31;
    int batch = blockIdx.x * 2 + (threadIdx.x >> 5);
    int na = g_na;
    if      (na <= 4)  scan_body<4 >(lane, batch, gleak, vleak, cm, ow, ob, out);
    else if (na <= 6)  scan_body<6 >(lane, batch, gleak, vleak, cm, ow, ob, out);
    else if (na <= 8)  scan_body<8 >(lane, batch, gleak, vleak, cm, ow, ob, out);
    else if (na <= 10) scan_body<10>(lane, batch, gleak, vleak, cm, ow, ob, out);
    else if (na <= 12) scan_body<12>(lane, batch, gleak, vleak, cm, ow, ob, out);
    else               scan_body<18>(lane, batch, gleak, vleak, cm, ow, ob, out);
}

// ---------------------------------------------------------------------------
extern "C" void kernel_launch(void* const* d_in, const int* in_sizes, int n_in,
                              void* d_out, int out_size)
{
    const float* x    = (const float*)d_in[0];
    const float* d1w  = (const float*)d_in[1];
    const float* d1b  = (const float*)d_in[2];
    const float* d2w  = (const float*)d_in[3];
    const float* d2b  = (const float*)d_in[4];
    const float* iw   = (const float*)d_in[5];
    const float* ib   = (const float*)d_in[6];
    const float* ow   = (const float*)d_in[7];
    const float* ob   = (const float*)d_in[8];
    const float* gle  = (const float*)d_in[9];
    const float* vle  = (const float*)d_in[10];
    const float* cmv  = (const float*)d_in[11];
    const float* wsyn = (const float*)d_in[12];
    const float* muv  = (const float*)d_in[13];
    const float* sgv  = (const float*)d_in[14];
    const float* erv  = (const float*)d_in[15];
    const float* swv  = (const float*)d_in[16];
    const float* smuv = (const float*)d_in[17];
    const float* ssgv = (const float*)d_in[18];
    const float* serv = (const float*)d_in[19];
    const int*   spm  = (const int*)d_in[20];
    const int*   ssm  = (const int*)d_in[21];

    setup_kernel<<<1, 32>>>(spm, wsyn, muv, sgv, erv, ssm, swv, smuv, ssgv, serv);
    sens_kernel<<<(BDIM * TDIM) / 4, 128>>>(x, d1w, d1b, d2w, d2b, iw, ib);
    scan_kernel<<<BDIM / 2, 64>>>(gle, vle, cmv, ow, ob, (float*)d_out);
}

// round 3
// speedup vs baseline: 1.4452x; 1.4452x over previous
#include <cuda_runtime.h>
#include <cstdint>

#define BDIM 256
#define TDIM 1024
#define U    32
#define UNF  6
#define EPSV 1e-8f
#define AMAX 18
#define SMAX 32
#define FULLM 0xffffffffu

// 64 MB scratch: precomputed sensory (num, den) per (b,t,unit)
__device__ float2 g_sens[(size_t)BDIM * TDIM * U];

// per-column sparse recurrent lists (tanh form), layout [k*U + col]
__device__ int   g_asrc[AMAX * U];
__device__ float g_aa[AMAX * U], g_ab[AMAX * U], g_aweh[AMAX * U], g_awdh[AMAX * U];
__device__ float g_anum0[U], g_aden0[U];
__device__ int   g_na;

// per-column sparse sensory lists (tanh form)
__device__ int   g_ssrc[SMAX * U];
__device__ float g_sa[SMAX * U], g_sb[SMAX * U], g_sweh[SMAX * U], g_swdh[SMAX * U];
__device__ float g_snum0[U], g_sden0[U];
__device__ int   g_ns;

__device__ __forceinline__ float tanhf_a(float x) {
    float r; asm("tanh.approx.f32 %0, %1;" : "=f"(r) : "f"(x)); return r;
}
__device__ __forceinline__ float rcpf(float x) {
    float r; asm("rcp.approx.ftz.f32 %0, %1;" : "=f"(r) : "f"(x)); return r;
}

// ---------------------------------------------------------------------------
// Setup: 1024 threads stage all params into shared; 64 threads build lists.
// sigmoid(s(v-mu)) = 0.5 + 0.5*tanh(a*v - b), a = 0.5*s, b = 0.5*s*mu.
// Constant halves fold into num0/den0.
// ---------------------------------------------------------------------------
__global__ void __launch_bounds__(1024) setup_kernel(
    const int* __restrict__ spm, const float* __restrict__ wsyn,
    const float* __restrict__ mu, const float* __restrict__ sg,
    const float* __restrict__ er,
    const int* __restrict__ ssm, const float* __restrict__ sw,
    const float* __restrict__ smu, const float* __restrict__ ssg,
    const float* __restrict__ ser)
{
    __shared__ int   s_m[1024]; __shared__ float s_w[1024], s_mu[1024], s_sg[1024], s_er[1024];
    __shared__ int   t_m[1024]; __shared__ float t_w[1024], t_mu[1024], t_sg[1024], t_er[1024];
    int tid = threadIdx.x;
    s_m[tid] = spm[tid]; s_w[tid] = wsyn[tid]; s_mu[tid] = mu[tid];
    s_sg[tid] = sg[tid]; s_er[tid] = er[tid];
    t_m[tid] = ssm[tid]; t_w[tid] = sw[tid];  t_mu[tid] = smu[tid];
    t_sg[tid] = ssg[tid]; t_er[tid] = ser[tid];
    __syncthreads();

    if (tid < 32) {                       // recurrent lists, column j = tid
        int j = tid, cnt = 0;
        float n0 = 0.f, d0 = 0.f;
        for (int i = 0; i < U; i++) {
            int idx = i * U + j;
            if (s_m[idx] != 0 && cnt < AMAX) {
                float a = 0.5f * s_sg[idx];
                float weh = 0.5f * s_w[idx] * s_er[idx];
                float wdh = 0.5f * s_w[idx];
                g_asrc[cnt * U + j] = i;
                g_aa[cnt * U + j]   = a;
                g_ab[cnt * U + j]   = a * s_mu[idx];
                g_aweh[cnt * U + j] = weh;
                g_awdh[cnt * U + j] = wdh;
                n0 += weh; d0 += wdh;
                cnt++;
            }
        }
        for (int k = cnt; k < AMAX; k++) {
            g_asrc[k * U + j] = 0;
            g_aa[k * U + j] = 0.f; g_ab[k * U + j] = 0.f;
            g_aweh[k * U + j] = 0.f; g_awdh[k * U + j] = 0.f;
        }
        g_anum0[j] = n0; g_aden0[j] = d0;
        int m = cnt;
        #pragma unroll
        for (int o = 16; o > 0; o >>= 1) m = max(m, __shfl_xor_sync(FULLM, m, o));
        if (j == 0) g_na = m;
    } else if (tid < 64) {                // sensory lists, column j = tid-32
        int j = tid - 32, cnt = 0;
        float n0 = 0.f, d0 = 0.f;
        for (int i = 0; i < U; i++) {
            int idx = i * U + j;
            if (t_m[idx] != 0 && cnt < SMAX) {
                float a = 0.5f * t_sg[idx];
                float weh = 0.5f * t_w[idx] * t_er[idx];
                float wdh = 0.5f * t_w[idx];
                g_ssrc[cnt * U + j] = i;
                g_sa[cnt * U + j]   = a;
                g_sb[cnt * U + j]   = a * t_mu[idx];
                g_sweh[cnt * U + j] = weh;
                g_swdh[cnt * U + j] = wdh;
                n0 += weh; d0 += wdh;
                cnt++;
            }
        }
        for (int k = cnt; k < SMAX; k++) {
            g_ssrc[k * U + j] = 0;
            g_sa[k * U + j] = 0.f; g_sb[k * U + j] = 0.f;
            g_sweh[k * U + j] = 0.f; g_swdh[k * U + j] = 0.f;
        }
        g_snum0[j] = n0; g_sden0[j] = d0;
        int m = cnt;
        #pragma unroll
        for (int o = 16; o > 0; o >>= 1) m = max(m, __shfl_xor_sync(FULLM, m, o));
        if (j == 0) g_ns = m;             // FIXED (was j == 32: never true -> g_ns stayed 0)
    }
}

// ---------------------------------------------------------------------------
// Precompute: dense stack + sensory sums. 8 warps/block, 8 rows/warp.
// d2_w is loaded once per 8 rows (L1 traffic /8 vs row-per-warp).
// ---------------------------------------------------------------------------
__global__ void __launch_bounds__(256) sens_kernel(
    const float* __restrict__ x,
    const float* __restrict__ d1w, const float* __restrict__ d1b,
    const float* __restrict__ d2w, const float* __restrict__ d2b,
    const float* __restrict__ iw,  const float* __restrict__ ib)
{
    __shared__ float sh_h1[8][8][128];
    __shared__ float sh_in[8][8][32];
    int warp = threadIdx.x >> 5, lane = threadIdx.x & 31;
    size_t row0 = ((size_t)blockIdx.x * 8 + warp) * 8;

    float2 xv = make_float2(0.f, 0.f);
    if (lane < 8) xv = ((const float2*)x)[row0 + lane];

    float wa[4], wb[4], bb[4];
    #pragma unroll
    for (int c = 0; c < 4; c++) {
        int k = c * 32 + lane;
        wa[c] = d1w[k]; wb[c] = d1w[128 + k]; bb[c] = d1b[k];
    }
    #pragma unroll
    for (int r = 0; r < 8; r++) {
        float x0 = __shfl_sync(FULLM, xv.x, r);
        float x1 = __shfl_sync(FULLM, xv.y, r);
        #pragma unroll
        for (int c = 0; c < 4; c++) {
            int k = c * 32 + lane;
            sh_h1[warp][r][k] = fmaxf(fmaf(x0, wa[c], fmaf(x1, wb[c], bb[c])), 0.f);
        }
    }
    __syncwarp();

    float acc[8];
    float dbl = d2b[lane];
    #pragma unroll
    for (int r = 0; r < 8; r++) acc[r] = dbl;
    #pragma unroll 4
    for (int k = 0; k < 128; k++) {
        float w2 = d2w[k * 32 + lane];
        #pragma unroll
        for (int r = 0; r < 8; r++) acc[r] = fmaf(sh_h1[warp][r][k], w2, acc[r]);
    }
    float iwl = iw[lane], ibl = ib[lane];
    #pragma unroll
    for (int r = 0; r < 8; r++) sh_in[warp][r][lane] = fmaf(acc[r], iwl, ibl);
    __syncwarp();

    float num[8], den[8];
    float n0 = g_snum0[lane], d0 = g_sden0[lane];
    #pragma unroll
    for (int r = 0; r < 8; r++) { num[r] = n0; den[r] = d0; }

    int ns = g_ns;
    for (int k = 0; k < ns; k++) {
        int   src = g_ssrc[k * U + lane];
        float a   = g_sa[k * U + lane];
        float b   = g_sb[k * U + lane];
        float weh = g_sweh[k * U + lane];
        float wdh = g_swdh[k * U + lane];
        #pragma unroll
        for (int r = 0; r < 8; r++) {
            float t = tanhf_a(fmaf(a, sh_in[warp][r][src], -b));
            num[r] = fmaf(weh, t, num[r]);
            den[r] = fmaf(wdh, t, den[r]);
        }
    }
    #pragma unroll
    for (int r = 0; r < 8; r++)
        g_sens[(row0 + r) * U + lane] = make_float2(num[r], den[r]);
}

// ---------------------------------------------------------------------------
// Sequential scan: warp per batch, lane = unit. tanh-form synapses,
// pairwise accumulation trees, hoisted per-timestep constants.
// ---------------------------------------------------------------------------
template <int NA>
__device__ __forceinline__ void scan_body(
    int lane, int batch,
    const float* __restrict__ gleak, const float* __restrict__ vleak,
    const float* __restrict__ cm,
    const float* __restrict__ ow, const float* __restrict__ ob,
    float* __restrict__ out)
{
    float gl   = gleak[lane];
    float cmt  = cm[lane] * (float)UNF;
    float gv   = gl * vleak[lane];
    float dcst = cmt + gl + EPSV + g_aden0[lane];
    float ncst = g_anum0[lane];

    int src[NA]; float a[NA], b[NA], weh[NA], wdh[NA];
    #pragma unroll
    for (int k = 0; k < NA; k++) {
        src[k] = g_asrc[k * U + lane];
        a[k]   = g_aa[k * U + lane];
        b[k]   = g_ab[k * U + lane];
        weh[k] = g_aweh[k * U + lane];
        wdh[k] = g_awdh[k * U + lane];
    }

    const float2* sp = g_sens + (size_t)batch * TDIM * U + lane;
    float v = 0.f;
    float2 sv = sp[0];

    for (int t = 0; t < TDIM; t++) {
        int tn = (t + 1 < TDIM) ? (t + 1) : t;
        float2 nxt = sp[(size_t)tn * U];       // prefetch; hidden under 6 unfolds

        float nb = sv.x + ncst;
        float db = sv.y + dcst;

        #pragma unroll
        for (int u = 0; u < UNF; u++) {
            float p = fmaf(cmt, v, gv);        // off the tanh critical path
            float tk[NA];
            #pragma unroll
            for (int k = 0; k < NA; k++) {
                float vs = __shfl_sync(FULLM, v, src[k]);
                tk[k] = tanhf_a(fmaf(a[k], vs, -b[k]));
            }
            // pairwise accumulation trees
            float nacc[NA], dacc[NA];
            #pragma unroll
            for (int k = 0; k < NA; k++) { nacc[k] = weh[k] * tk[k]; dacc[k] = wdh[k] * tk[k]; }
            #pragma unroll
            for (int s = 1; s < NA; s <<= 1) {
                #pragma unroll
                for (int k = 0; k + s < NA; k += 2 * s) {
                    nacc[k] += nacc[k + s];
                    dacc[k] += dacc[k + s];
                }
            }
            float num = nb + nacc[0];
            float den = db + dacc[0];
            v = (p + num) * rcpf(den);
        }
        sv = nxt;
    }

    if (lane == 0) out[batch] = fmaf(v, ow[0], ob[0]);
}

__global__ void __launch_bounds__(64) scan_kernel(
    const float* __restrict__ gleak, const float* __restrict__ vleak,
    const float* __restrict__ cm,
    const float* __restrict__ ow, const float* __restrict__ ob,
    float* __restrict__ out)
{
    int lane  = threadIdx.x & 31;
    int batch = blockIdx.x * 2 + (threadIdx.x >> 5);
    int na = g_na;
    if      (na <= 4)  scan_body<4 >(lane, batch, gleak, vleak, cm, ow, ob, out);
    else if (na <= 6)  scan_body<6 >(lane, batch, gleak, vleak, cm, ow, ob, out);
    else if (na <= 8)  scan_body<8 >(lane, batch, gleak, vleak, cm, ow, ob, out);
    else if (na <= 10) scan_body<10>(lane, batch, gleak, vleak, cm, ow, ob, out);
    else if (na <= 12) scan_body<12>(lane, batch, gleak, vleak, cm, ow, ob, out);
    else               scan_body<18>(lane, batch, gleak, vleak, cm, ow, ob, out);
}

// ---------------------------------------------------------------------------
extern "C" void kernel_launch(void* const* d_in, const int* in_sizes, int n_in,
                              void* d_out, int out_size)
{
    const float* x    = (const float*)d_in[0];
    const float* d1w  = (const float*)d_in[1];
    const float* d1b  = (const float*)d_in[2];
    const float* d2w  = (const float*)d_in[3];
    const float* d2b  = (const float*)d_in[4];
    const float* iw   = (const float*)d_in[5];
    const float* ib   = (const float*)d_in[6];
    const float* ow   = (const float*)d_in[7];
    const float* ob   = (const float*)d_in[8];
    const float* gle  = (const float*)d_in[9];
    const float* vle  = (const float*)d_in[10];
    const float* cmv  = (const float*)d_in[11];
    const float* wsyn = (const float*)d_in[12];
    const float* muv  = (const float*)d_in[13];
    const float* sgv  = (const float*)d_in[14];
    const float* erv  = (const float*)d_in[15];
    const float* swv  = (const float*)d_in[16];
    const float* smuv = (const float*)d_in[17];
    const float* ssgv = (const float*)d_in[18];
    const float* serv = (const float*)d_in[19];
    const int*   spm  = (const int*)d_in[20];
    const int*   ssm  = (const int*)d_in[21];

    setup_kernel<<<1, 1024>>>(spm, wsyn, muv, sgv, erv, ssm, swv, smuv, ssgv, serv);
    sens_kernel<<<(BDIM * TDIM) / 64, 256>>>(x, d1w, d1b, d2w, d2b, iw, ib);
    scan_kernel<<<BDIM / 2, 64>>>(gle, vle, cmv, ow, ob, (float*)d_out);
}

// round 4
// speedup vs baseline: 1.5541x; 1.0754x over previous
#include <cuda_runtime.h>
#include <cstdint>

#define BDIM 256
#define TDIM 1024
#define U    32
#define UNF  6
#define EPSV 1e-8f
#define AMAX 18
#define SMAX 32
#define FULLM 0xffffffffu
#define NTICK (TDIM * (BDIM / 8))   // 32768 tickets, 8 batch-rows each

// 64 MB scratch: precomputed sensory (num, den) per (b,t,unit)
__device__ float2 g_sens[(size_t)BDIM * TDIM * U];
// per-timestep completion counters (32 tickets per t)
__device__ int g_cnt[TDIM];

// per-column sparse recurrent lists (tanh form), layout [k*U + col]
__device__ int   g_asrc[AMAX * U];
__device__ float g_aa[AMAX * U], g_ab[AMAX * U], g_aweh[AMAX * U], g_awdh[AMAX * U];
__device__ float g_anum0[U], g_aden0[U];
__device__ int   g_na;

// per-column sparse sensory lists (tanh form)
__device__ int   g_ssrc[SMAX * U];
__device__ float g_sa[SMAX * U], g_sb[SMAX * U], g_sweh[SMAX * U], g_swdh[SMAX * U];
__device__ float g_snum0[U], g_sden0[U];
__device__ int   g_ns;

__device__ __forceinline__ float tanhf_a(float x) {
    float r; asm("tanh.approx.f32 %0, %1;" : "=f"(r) : "f"(x)); return r;
}
__device__ __forceinline__ float rcpf(float x) {
    float r; asm("rcp.approx.ftz.f32 %0, %1;" : "=f"(r) : "f"(x)); return r;
}
__device__ __forceinline__ int ld_acq(const int* p) {
    int v; asm volatile("ld.acquire.gpu.global.b32 %0, [%1];" : "=r"(v) : "l"(p)); return v;
}

// ---------------------------------------------------------------------------
// Setup: build lists (tanh form) + zero the per-t counters.
// sigmoid(s(v-mu)) = 0.5 + 0.5*tanh(a*v - b), a = 0.5*s, b = 0.5*s*mu.
// ---------------------------------------------------------------------------
__global__ void __launch_bounds__(1024) setup_kernel(
    const int* __restrict__ spm, const float* __restrict__ wsyn,
    const float* __restrict__ mu, const float* __restrict__ sg,
    const float* __restrict__ er,
    const int* __restrict__ ssm, const float* __restrict__ sw,
    const float* __restrict__ smu, const float* __restrict__ ssg,
    const float* __restrict__ ser)
{
    __shared__ int   s_m[1024]; __shared__ float s_w[1024], s_mu[1024], s_sg[1024], s_er[1024];
    __shared__ int   t_m[1024]; __shared__ float t_w[1024], t_mu[1024], t_sg[1024], t_er[1024];
    int tid = threadIdx.x;
    g_cnt[tid] = 0;                            // reset readiness counters (every launch)
    s_m[tid] = spm[tid]; s_w[tid] = wsyn[tid]; s_mu[tid] = mu[tid];
    s_sg[tid] = sg[tid]; s_er[tid] = er[tid];
    t_m[tid] = ssm[tid]; t_w[tid] = sw[tid];  t_mu[tid] = smu[tid];
    t_sg[tid] = ssg[tid]; t_er[tid] = ser[tid];
    __syncthreads();

    if (tid < 32) {                       // recurrent lists, column j = tid
        int j = tid, cnt = 0;
        float n0 = 0.f, d0 = 0.f;
        for (int i = 0; i < U; i++) {
            int idx = i * U + j;
            if (s_m[idx] != 0 && cnt < AMAX) {
                float a = 0.5f * s_sg[idx];
                float weh = 0.5f * s_w[idx] * s_er[idx];
                float wdh = 0.5f * s_w[idx];
                g_asrc[cnt * U + j] = i;
                g_aa[cnt * U + j]   = a;
                g_ab[cnt * U + j]   = a * s_mu[idx];
                g_aweh[cnt * U + j] = weh;
                g_awdh[cnt * U + j] = wdh;
                n0 += weh; d0 += wdh;
                cnt++;
            }
        }
        for (int k = cnt; k < AMAX; k++) {
            g_asrc[k * U + j] = 0;
            g_aa[k * U + j] = 0.f; g_ab[k * U + j] = 0.f;
            g_aweh[k * U + j] = 0.f; g_awdh[k * U + j] = 0.f;
        }
        g_anum0[j] = n0; g_aden0[j] = d0;
        int m = cnt;
        #pragma unroll
        for (int o = 16; o > 0; o >>= 1) m = max(m, __shfl_xor_sync(FULLM, m, o));
        if (j == 0) g_na = m;
    } else if (tid < 64) {                // sensory lists, column j = tid-32
        int j = tid - 32, cnt = 0;
        float n0 = 0.f, d0 = 0.f;
        for (int i = 0; i < U; i++) {
            int idx = i * U + j;
            if (t_m[idx] != 0 && cnt < SMAX) {
                float a = 0.5f * t_sg[idx];
                float weh = 0.5f * t_w[idx] * t_er[idx];
                float wdh = 0.5f * t_w[idx];
                g_ssrc[cnt * U + j] = i;
                g_sa[cnt * U + j]   = a;
                g_sb[cnt * U + j]   = a * t_mu[idx];
                g_sweh[cnt * U + j] = weh;
                g_swdh[cnt * U + j] = wdh;
                n0 += weh; d0 += wdh;
                cnt++;
            }
        }
        for (int k = cnt; k < SMAX; k++) {
            g_ssrc[k * U + j] = 0;
            g_sa[k * U + j] = 0.f; g_sb[k * U + j] = 0.f;
            g_sweh[k * U + j] = 0.f; g_swdh[k * U + j] = 0.f;
        }
        g_snum0[j] = n0; g_sden0[j] = d0;
        int m = cnt;
        #pragma unroll
        for (int o = 16; o > 0; o >>= 1) m = max(m, __shfl_xor_sync(FULLM, m, o));
        if (j == 0) g_ns = m;
    }
}

// ---------------------------------------------------------------------------
// Fused producer/consumer kernel.
// Blocks 0..127: warps 0,1 = scan (batches 2*bid, 2*bid+1), warps 2,3,6,7 = sens,
//                warps 4,5 exit (keep scan SMSPs free of sens MUFU traffic).
// Blocks >=128: all 8 warps = sens.
// ---------------------------------------------------------------------------

// sens worker: processes tickets (t, 8-batch group) in t-major static partition.
__device__ void sens_warp(
    int sw, int nw, int warp, int lane, float* smem,
    const float* __restrict__ x,
    const float* __restrict__ d1w, const float* __restrict__ d1b,
    const float* __restrict__ d2b,
    const float* __restrict__ iw,  const float* __restrict__ ib)
{
    float* sh_w2t = smem;                       // [32][132]
    float* sh_h1  = smem + 32 * 132 + warp * 1024;   // [8][128] per warp
    float* sh_in  = smem + 32 * 132 + 8 * 1024 + warp * 256; // [8][32] per warp

    // hoisted per-warp constants
    float wa[4], wb[4], bb[4];
    #pragma unroll
    for (int c = 0; c < 4; c++) {
        int k = c * 32 + lane;
        wa[c] = d1w[k]; wb[c] = d1w[128 + k]; bb[c] = d1b[k];
    }
    float dbl = d2b[lane], iwl = iw[lane], ibl = ib[lane];
    float n0 = g_snum0[lane], d0 = g_sden0[lane];
    int ns = g_ns;

    for (int q = sw; q < NTICK; q += nw) {
        int t  = q >> 5;
        int b0 = (q & 31) << 3;

        float2 xv = make_float2(0.f, 0.f);
        if (lane < 8) xv = ((const float2*)x)[(size_t)(b0 + lane) * TDIM + t];

        #pragma unroll
        for (int r = 0; r < 8; r++) {
            float x0 = __shfl_sync(FULLM, xv.x, r);
            float x1 = __shfl_sync(FULLM, xv.y, r);
            #pragma unroll
            for (int c = 0; c < 4; c++) {
                int k = c * 32 + lane;
                sh_h1[r * 128 + k] = fmaxf(fmaf(x0, wa[c], fmaf(x1, wb[c], bb[c])), 0.f);
            }
        }
        __syncwarp();

        float acc[8];
        #pragma unroll
        for (int r = 0; r < 8; r++) acc[r] = dbl;
        #pragma unroll 8
        for (int kq = 0; kq < 32; kq++) {
            float4 w4 = *(const float4*)&sh_w2t[lane * 132 + kq * 4];
            #pragma unroll
            for (int r = 0; r < 8; r++) {
                float4 h4 = *(const float4*)&sh_h1[r * 128 + kq * 4];
                acc[r] = fmaf(h4.x, w4.x, acc[r]);
                acc[r] = fmaf(h4.y, w4.y, acc[r]);
                acc[r] = fmaf(h4.z, w4.z, acc[r]);
                acc[r] = fmaf(h4.w, w4.w, acc[r]);
            }
        }
        #pragma unroll
        for (int r = 0; r < 8; r++) sh_in[r * 32 + lane] = fmaf(acc[r], iwl, ibl);
        __syncwarp();

        float num[8], den[8];
        #pragma unroll
        for (int r = 0; r < 8; r++) { num[r] = n0; den[r] = d0; }
        for (int k = 0; k < ns; k++) {
            int   src = g_ssrc[k * U + lane];
            float a   = g_sa[k * U + lane];
            float b   = g_sb[k * U + lane];
            float weh = g_sweh[k * U + lane];
            float wdh = g_swdh[k * U + lane];
            #pragma unroll
            for (int r = 0; r < 8; r++) {
                float tk = tanhf_a(fmaf(a, sh_in[r * 32 + src], -b));
                num[r] = fmaf(weh, tk, num[r]);
                den[r] = fmaf(wdh, tk, den[r]);
            }
        }
        #pragma unroll
        for (int r = 0; r < 8; r++)
            g_sens[((size_t)(b0 + r) * TDIM + t) * U + lane] = make_float2(num[r], den[r]);

        __threadfence();                        // release: data before counter
        if (lane == 0) atomicAdd(&g_cnt[t], 1);
        __syncwarp();
    }
}

// verify 8 timesteps [base, base+8) are fully produced (32 tickets each)
__device__ __forceinline__ void verify8(int base) {
    for (;;) {
        int ok = 1;
        #pragma unroll
        for (int i = 0; i < 8; i++)
            ok &= (ld_acq(&g_cnt[base + i]) == 32);
        if (ok) return;
        __nanosleep(200);
    }
}

template <int NA>
__device__ void scan_body(
    int lane, int batch,
    const float* __restrict__ gleak, const float* __restrict__ vleak,
    const float* __restrict__ cm,
    const float* __restrict__ ow, const float* __restrict__ ob,
    float* __restrict__ out)
{
    float gl   = gleak[lane];
    float cmt  = cm[lane] * (float)UNF;
    float gv   = gl * vleak[lane];
    float dcst = cmt + gl + EPSV + g_aden0[lane];
    float ncst = g_anum0[lane];

    int src[NA]; float a[NA], b[NA], weh[NA], wdh[NA];
    #pragma unroll
    for (int k = 0; k < NA; k++) {
        src[k] = g_asrc[k * U + lane];
        a[k]   = g_aa[k * U + lane];
        b[k]   = g_ab[k * U + lane];
        weh[k] = g_aweh[k * U + lane];
        wdh[k] = g_awdh[k * U + lane];
    }

    const float2* sp = g_sens + (size_t)batch * TDIM * U + lane;

    verify8(0);
    float2 sv = sp[0];
    float v = 0.f;

    for (int t = 0; t < TDIM; t++) {
        if ((t & 7) == 0 && t + 8 < TDIM) verify8(t + 8);  // stay 8 steps ahead
        int tn = (t + 1 < TDIM) ? (t + 1) : t;
        float2 nxt = sp[(size_t)tn * U];

        float nb = sv.x + ncst;
        float db = sv.y + dcst;

        #pragma unroll
        for (int u = 0; u < UNF; u++) {
            float p = fmaf(cmt, v, gv);
            float tk[NA];
            #pragma unroll
            for (int k = 0; k < NA; k++) {
                float vs = __shfl_sync(FULLM, v, src[k]);
                tk[k] = tanhf_a(fmaf(a[k], vs, -b[k]));
            }
            // 4-way interleaved fma chains (low register pressure, depth ~NA)
            float nch[4], dch[4];
            nch[0] = p + nb; nch[1] = 0.f; nch[2] = 0.f; nch[3] = 0.f;
            dch[0] = db;     dch[1] = 0.f; dch[2] = 0.f; dch[3] = 0.f;
            #pragma unroll
            for (int k = 0; k < NA; k++) {
                nch[k & 3] = fmaf(weh[k], tk[k], nch[k & 3]);
                dch[k & 3] = fmaf(wdh[k], tk[k], dch[k & 3]);
            }
            float num = (nch[0] + nch[1]) + (nch[2] + nch[3]);
            float den = (dch[0] + dch[1]) + (dch[2] + dch[3]);
            v = num * rcpf(den);
        }
        sv = nxt;
    }

    if (lane == 0) out[batch] = fmaf(v, ow[0], ob[0]);
}

__global__ void __launch_bounds__(256) fused_kernel(
    const float* __restrict__ x,
    const float* __restrict__ d1w, const float* __restrict__ d1b,
    const float* __restrict__ d2w, const float* __restrict__ d2b,
    const float* __restrict__ iw,  const float* __restrict__ ib,
    const float* __restrict__ gleak, const float* __restrict__ vleak,
    const float* __restrict__ cm,
    const float* __restrict__ ow, const float* __restrict__ ob,
    float* __restrict__ out)
{
    extern __shared__ float smem[];
    int tid = threadIdx.x, warp = tid >> 5, lane = tid & 31;

    // stage d2_w transposed [j][k] padded to 132 (conflict-free float4 column reads)
    for (int i = tid; i < 128 * 32; i += 256) {
        int k = i >> 5, j = i & 31;
        smem[j * 132 + k] = d2w[i];
    }
    __syncthreads();

    bool scanBlk = (blockIdx.x < 128);
    if (scanBlk && warp < 2) {
        int batch = blockIdx.x * 2 + warp;
        int na = g_na;
        if      (na <= 4)  scan_body<4 >(lane, batch, gleak, vleak, cm, ow, ob, out);
        else if (na <= 6)  scan_body<6 >(lane, batch, gleak, vleak, cm, ow, ob, out);
        else if (na <= 8)  scan_body<8 >(lane, batch, gleak, vleak, cm, ow, ob, out);
        else if (na <= 10) scan_body<10>(lane, batch, gleak, vleak, cm, ow, ob, out);
        else if (na <= 12) scan_body<12>(lane, batch, gleak, vleak, cm, ow, ob, out);
        else               scan_body<18>(lane, batch, gleak, vleak, cm, ow, ob, out);
    } else if (scanBlk) {
        if (warp == 4 || warp == 5) return;     // keep SMSP 0/1 for scan warps
        int idx = (warp >= 6) ? (warp - 4) : (warp - 2);  // {2,3,6,7} -> {0,1,2,3}
        int sw = blockIdx.x * 4 + idx;
        int nw = 128 * 4 + (gridDim.x - 128) * 8;
        sens_warp(sw, nw, warp, lane, smem, x, d1w, d1b, d2b, iw, ib);
    } else {
        int sw = 128 * 4 + (blockIdx.x - 128) * 8 + warp;
        int nw = 128 * 4 + (gridDim.x - 128) * 8;
        sens_warp(sw, nw, warp, lane, smem, x, d1w, d1b, d2b, iw, ib);
    }
}

// ---------------------------------------------------------------------------
extern "C" void kernel_launch(void* const* d_in, const int* in_sizes, int n_in,
                              void* d_out, int out_size)
{
    const float* x    = (const float*)d_in[0];
    const float* d1w  = (const float*)d_in[1];
    const float* d1b  = (const float*)d_in[2];
    const float* d2w  = (const float*)d_in[3];
    const float* d2b  = (const float*)d_in[4];
    const float* iw   = (const float*)d_in[5];
    const float* ib   = (const float*)d_in[6];
    const float* ow   = (const float*)d_in[7];
    const float* ob   = (const float*)d_in[8];
    const float* gle  = (const float*)d_in[9];
    const float* vle  = (const float*)d_in[10];
    const float* cmv  = (const float*)d_in[11];
    const float* wsyn = (const float*)d_in[12];
    const float* muv  = (const float*)d_in[13];
    const float* sgv  = (const float*)d_in[14];
    const float* erv  = (const float*)d_in[15];
    const float* swv  = (const float*)d_in[16];
    const float* smuv = (const float*)d_in[17];
    const float* ssgv = (const float*)d_in[18];
    const float* serv = (const float*)d_in[19];
    const int*   spm  = (const int*)d_in[20];
    const int*   ssm  = (const int*)d_in[21];

    int nsm = 148;
    cudaDeviceGetAttribute(&nsm, cudaDevAttrMultiProcessorCount, 0);
    int blocks = (nsm > 128) ? nsm : 129;   // >=129 so at least 1 all-sens block

    const int smemBytes = (32 * 132 + 8 * 1024 + 8 * 256) * sizeof(float); // ~57.5 KB
    static_assert((32 * 132 + 8 * 1024 + 8 * 256) * sizeof(float) < 100 * 1024, "");
    cudaFuncSetAttribute(fused_kernel, cudaFuncAttributeMaxDynamicSharedMemorySize, smemBytes);

    setup_kernel<<<1, 1024>>>(spm, wsyn, muv, sgv, erv, ssm, swv, smuv, ssgv, serv);
    fused_kernel<<<blocks, 256, smemBytes>>>(x, d1w, d1b, d2w, d2b, iw, ib,
                                             gle, vle, cmv, ow, ob, (float*)d_out);
}